// round 1
// baseline (speedup 1.0000x reference)
#include <cuda_runtime.h>
#include <math.h>
#include <float.h>
#include <stdint.h>

#define BTOT 8
#define SEQ  2048
#define MTOK (BTOT*SEQ)   /* 16384 */
#define DM   256
#define DQK  128
#define NH   8
#define DH   16
#define DV   32
#define NKNN 16
#define DFF  1024

// ---------------- scratch (static device globals; no allocations) ----------------
__device__ float g_q  [MTOK*DQK];
__device__ float g_k  [MTOK*DQK];
__device__ float g_kk [MTOK];
__device__ float g_S  [33554432];      // 8 * 2048 * 2048
__device__ int   g_idx[MTOK*NKNN];
__device__ float g_ln [MTOK*DM];
__device__ float g_u  [MTOK*DM];
__device__ float g_o  [MTOK*DM];
__device__ float g_y1 [MTOK*DM];
__device__ float g_h  [MTOK*DFF];

// ---------------- generic tiled SGEMM: C = epi(A @ B(+ᵀ) , bias, extra) ----------
// BM=BN=128, BK=16, 256 threads, 8x8 thread tile.
// EPI: 0 = acc+bias ; 1 = extra[col] - 2*acc (score) ;
//      2 = gelu(acc+bias) ; 3 = extra[row,col] + rw*(acc+bias)
template<bool BT, int EPI>
__global__ void __launch_bounds__(256)
gemm_k(const float* __restrict__ A, const float* __restrict__ Bm,
       const float* __restrict__ bias, float* __restrict__ C,
       int Kdim, int Ndim,
       const float* __restrict__ extra, const float* __restrict__ rwp,
       long long sAz, long long sBz, long long sCz, long long sEz)
{
    __shared__ float As[16][128];
    __shared__ float Bs[16][128];
    const int bz = blockIdx.z;
    A  += (long long)bz * sAz;
    Bm += (long long)bz * sBz;
    C  += (long long)bz * sCz;
    if (EPI == 1) extra += (long long)bz * sEz;

    const int m0 = blockIdx.y * 128;
    const int n0 = blockIdx.x * 128;
    const int tid = threadIdx.x;

    float acc[8][8];
#pragma unroll
    for (int i = 0; i < 8; i++)
#pragma unroll
        for (int j = 0; j < 8; j++) acc[i][j] = 0.0f;

    const int ar = tid >> 2;          // 0..63
    const int ac = (tid & 3) << 2;    // 0,4,8,12

    for (int k0 = 0; k0 < Kdim; k0 += 16) {
        // A tile: [128 rows x 16 k], stored transposed As[k][m]
#pragma unroll
        for (int p = 0; p < 2; p++) {
            int r = ar + p * 64;
            float4 v = *(const float4*)(A + (long long)(m0 + r) * Kdim + k0 + ac);
            As[ac + 0][r] = v.x; As[ac + 1][r] = v.y;
            As[ac + 2][r] = v.z; As[ac + 3][r] = v.w;
        }
        if (BT) {
            // B stored [N, K] row-major (e.g. kn): load along K
#pragma unroll
            for (int p = 0; p < 2; p++) {
                int n = ar + p * 64;
                float4 v = *(const float4*)(Bm + (long long)(n0 + n) * Kdim + k0 + ac);
                Bs[ac + 0][n] = v.x; Bs[ac + 1][n] = v.y;
                Bs[ac + 2][n] = v.z; Bs[ac + 3][n] = v.w;
            }
        } else {
            // B stored [K, N] row-major (weights): load along N
#pragma unroll
            for (int p = 0; p < 2; p++) {
                int kr = (tid >> 5) + p * 8;
                int nc = (tid & 31) << 2;
                *(float4*)&Bs[kr][nc] =
                    *(const float4*)(Bm + (long long)(k0 + kr) * Ndim + n0 + nc);
            }
        }
        __syncthreads();
#pragma unroll
        for (int k = 0; k < 16; k++) {
            float a[8], b[8];
            *(float4*)&a[0] = *(const float4*)&As[k][(tid >> 4) * 8];
            *(float4*)&a[4] = *(const float4*)&As[k][(tid >> 4) * 8 + 4];
            *(float4*)&b[0] = *(const float4*)&Bs[k][(tid & 15) * 8];
            *(float4*)&b[4] = *(const float4*)&Bs[k][(tid & 15) * 8 + 4];
#pragma unroll
            for (int i = 0; i < 8; i++)
#pragma unroll
                for (int j = 0; j < 8; j++)
                    acc[i][j] = fmaf(a[i], b[j], acc[i][j]);
        }
        __syncthreads();
    }

    const float rw = (EPI == 3) ? rwp[0] : 0.0f;
#pragma unroll
    for (int i = 0; i < 8; i++) {
        int row = m0 + (tid >> 4) * 8 + i;
#pragma unroll
        for (int j = 0; j < 8; j++) {
            int col = n0 + (tid & 15) * 8 + j;
            float v = acc[i][j];
            if (EPI == 0) {
                v += bias[col];
            } else if (EPI == 1) {
                v = extra[col] - 2.0f * v;
            } else if (EPI == 2) {
                v += bias[col];
                v = 0.5f * v * (1.0f + erff(v * 0.7071067811865476f));
            } else if (EPI == 3) {
                v += bias[col];
                v = extra[(long long)row * Ndim + col] + rw * v;
            }
            C[(long long)row * Ndim + col] = v;
        }
    }
}

// ---------------- l2 normalize q & k rows (in place), kk = sum(kn^2) -------------
__global__ void __launch_bounds__(256) l2norm_k()
{
    int gw = (blockIdx.x * blockDim.x + threadIdx.x) >> 5;
    int lane = threadIdx.x & 31;
    if (gw >= 2 * MTOK) return;
    float* base = (gw < MTOK) ? (g_q + (long long)gw * DQK)
                              : (g_k + (long long)(gw - MTOK) * DQK);
    float4 v = *(float4*)(base + lane * 4);
    float ss = v.x * v.x + v.y * v.y + v.z * v.z + v.w * v.w;
#pragma unroll
    for (int o = 16; o; o >>= 1) ss += __shfl_xor_sync(0xffffffffu, ss, o);
    float inv = 1.0f / fmaxf(sqrtf(ss), 1e-12f);
    v.x *= inv; v.y *= inv; v.z *= inv; v.w *= inv;
    *(float4*)(base + lane * 4) = v;
    if (gw >= MTOK) {
        float s2 = v.x * v.x + v.y * v.y + v.z * v.z + v.w * v.w;
#pragma unroll
        for (int o = 16; o; o >>= 1) s2 += __shfl_xor_sync(0xffffffffu, s2, o);
        if (lane == 0) g_kk[gw - MTOK] = s2;
    }
}

// ---------------- LayerNorm over D=256 (warp per row) ----------------------------
__global__ void __launch_bounds__(256)
ln_k(const float* __restrict__ in, const float* __restrict__ g,
     const float* __restrict__ b, float* __restrict__ out)
{
    int gw = (blockIdx.x * blockDim.x + threadIdx.x) >> 5;
    int lane = threadIdx.x & 31;
    if (gw >= MTOK) return;
    const float* r = in + (long long)gw * DM;
    float4 a0 = *(const float4*)(r + lane * 8);
    float4 a1 = *(const float4*)(r + lane * 8 + 4);
    float s = a0.x + a0.y + a0.z + a0.w + a1.x + a1.y + a1.z + a1.w;
#pragma unroll
    for (int o = 16; o; o >>= 1) s += __shfl_xor_sync(0xffffffffu, s, o);
    float mean = s * (1.0f / 256.0f);
    float d0 = a0.x - mean, d1 = a0.y - mean, d2 = a0.z - mean, d3 = a0.w - mean;
    float d4 = a1.x - mean, d5 = a1.y - mean, d6 = a1.z - mean, d7 = a1.w - mean;
    float vs = d0*d0 + d1*d1 + d2*d2 + d3*d3 + d4*d4 + d5*d5 + d6*d6 + d7*d7;
#pragma unroll
    for (int o = 16; o; o >>= 1) vs += __shfl_xor_sync(0xffffffffu, vs, o);
    float is = rsqrtf(vs * (1.0f / 256.0f) + 1e-5f);
    float* w = out + (long long)gw * DM;
    int c = lane * 8;
    float4 o0, o1;
    o0.x = d0 * is * g[c+0] + b[c+0]; o0.y = d1 * is * g[c+1] + b[c+1];
    o0.z = d2 * is * g[c+2] + b[c+2]; o0.w = d3 * is * g[c+3] + b[c+3];
    o1.x = d4 * is * g[c+4] + b[c+4]; o1.y = d5 * is * g[c+5] + b[c+5];
    o1.z = d6 * is * g[c+6] + b[c+6]; o1.w = d7 * is * g[c+7] + b[c+7];
    *(float4*)(w + c) = o0;
    *(float4*)(w + c + 4) = o1;
}

// ---------------- top-16 smallest per score row (warp per row, smem staged) ------
__global__ void __launch_bounds__(128) topk_k()
{
    __shared__ float srow[4][SEQ];
    int wid = threadIdx.x >> 5, lane = threadIdx.x & 31;
    long long row = (long long)blockIdx.x * 4 + wid;
    const float* Sr = g_S + row * SEQ;
    float* sm = srow[wid];
    for (int c = lane; c < SEQ / 4; c += 32)
        *(float4*)(sm + c * 4) = *(const float4*)(Sr + c * 4);
    __syncwarp();
    int* orow = g_idx + row * NKNN;
    for (int r = 0; r < NKNN; r++) {
        float best = FLT_MAX; int bi = 0x7fffffff;
        for (int c = lane; c < SEQ; c += 32) {
            float s = sm[c];
            if (s < best || (s == best && c < bi)) { best = s; bi = c; }
        }
#pragma unroll
        for (int o = 16; o; o >>= 1) {
            float s2 = __shfl_xor_sync(0xffffffffu, best, o);
            int   i2 = __shfl_xor_sync(0xffffffffu, bi, o);
            if (s2 < best || (s2 == best && i2 < bi)) { best = s2; bi = i2; }
        }
        if (lane == 0) { orow[r] = bi; sm[bi] = FLT_MAX; }
        __syncwarp();
    }
}

// ---------------- attention combine: o[token] (thread = token x head) -------------
__global__ void __launch_bounds__(256) attn_k()
{
    int t = blockIdx.x * 256 + threadIdx.x;
    int token = t >> 3, h = t & 7;
    if (token >= MTOK) return;
    long long kbase = (long long)(token >> 11) * SEQ;

    const float* qp = g_q + (long long)token * DQK + h * DH;
    float q[16];
#pragma unroll
    for (int i = 0; i < 4; i++)
        *(float4*)&q[i * 4] = *(const float4*)(qp + i * 4);

    const int* ir = g_idx + (long long)token * NKNN;
    int nb[NKNN];
#pragma unroll
    for (int j = 0; j < NKNN; j++) nb[j] = ir[j];

    float lg[NKNN];
#pragma unroll
    for (int j = 0; j < NKNN; j++) {
        const float* kr = g_k + (kbase + nb[j]) * DQK + h * DH;
        float d = 0.0f;
#pragma unroll
        for (int i = 0; i < 4; i++) {
            float4 kv = *(const float4*)(kr + i * 4);
            d += q[i*4+0]*kv.x + q[i*4+1]*kv.y + q[i*4+2]*kv.z + q[i*4+3]*kv.w;
        }
        lg[j] = d * 0.25f;   // 1/sqrt(16)
    }
    float mx = lg[0];
#pragma unroll
    for (int j = 1; j < NKNN; j++) mx = fmaxf(mx, lg[j]);
    float se = 0.0f;
#pragma unroll
    for (int j = 0; j < NKNN; j++) { lg[j] = expf(lg[j] - mx); se += lg[j]; }
    float inv = 1.0f / se;

    float acc[32];
#pragma unroll
    for (int e = 0; e < 32; e++) acc[e] = 0.0f;
#pragma unroll
    for (int j = 0; j < NKNN; j++) {
        float w = lg[j] * inv;
        const float* ur = g_u + (kbase + nb[j]) * DM + h * DV;
#pragma unroll
        for (int i = 0; i < 8; i++) {
            float4 uv = *(const float4*)(ur + i * 4);
            acc[i*4+0] += w * uv.x; acc[i*4+1] += w * uv.y;
            acc[i*4+2] += w * uv.z; acc[i*4+3] += w * uv.w;
        }
    }
    float* op = g_o + (long long)token * DM + h * DV;
#pragma unroll
    for (int i = 0; i < 8; i++)
        *(float4*)(op + i * 4) =
            make_float4(acc[i*4+0], acc[i*4+1], acc[i*4+2], acc[i*4+3]);
}

// ---------------- launch sequence ------------------------------------------------
extern "C" void kernel_launch(void* const* d_in, const int* in_sizes, int n_in,
                              void* d_out, int out_size)
{
    const float* x   = (const float*)d_in[0];
    const float* Wq  = (const float*)d_in[1];
    const float* bq  = (const float*)d_in[2];
    const float* Wk  = (const float*)d_in[3];
    const float* bk  = (const float*)d_in[4];
    const float* Wv  = (const float*)d_in[5];
    const float* bv  = (const float*)d_in[6];
    const float* Wo  = (const float*)d_in[7];
    const float* bo  = (const float*)d_in[8];
    const float* g1v = (const float*)d_in[9];
    const float* b1v = (const float*)d_in[10];
    const float* gf  = (const float*)d_in[11];
    const float* bf  = (const float*)d_in[12];
    const float* W1  = (const float*)d_in[13];
    const float* b1f = (const float*)d_in[14];
    const float* W2  = (const float*)d_in[15];
    const float* b2f = (const float*)d_in[16];
    const float* rw  = (const float*)d_in[17];
    float* out = (float*)d_out;

    float *pq, *pk, *pkk, *pS, *pln, *pu, *po, *py1, *ph;
    cudaGetSymbolAddress((void**)&pq,  g_q);
    cudaGetSymbolAddress((void**)&pk,  g_k);
    cudaGetSymbolAddress((void**)&pkk, g_kk);
    cudaGetSymbolAddress((void**)&pS,  g_S);
    cudaGetSymbolAddress((void**)&pln, g_ln);
    cudaGetSymbolAddress((void**)&pu,  g_u);
    cudaGetSymbolAddress((void**)&po,  g_o);
    cudaGetSymbolAddress((void**)&py1, g_y1);
    cudaGetSymbolAddress((void**)&ph,  g_h);

    dim3 blk(256);

    // q / k projections: [16384,256] @ [256,128]
    gemm_k<false, 0><<<dim3(1, 128, 1), blk>>>(x, Wq, bq, pq, 256, 128,
                                               nullptr, nullptr, 0, 0, 0, 0);
    gemm_k<false, 0><<<dim3(1, 128, 1), blk>>>(x, Wk, bk, pk, 256, 128,
                                               nullptr, nullptr, 0, 0, 0, 0);
    // l2 normalize q, k (in place) + kk
    l2norm_k<<<4096, 256>>>();

    // scores: per batch S = kk[col] - 2 * qn @ kn^T   [2048 x 2048] x 8
    gemm_k<true, 1><<<dim3(16, 16, 8), blk>>>(pq, pk, nullptr, pS, 128, 2048,
                                              pkk, nullptr,
                                              (long long)SEQ * DQK,
                                              (long long)SEQ * DQK,
                                              (long long)SEQ * SEQ,
                                              (long long)SEQ);
    // top-16 nearest per query
    topk_k<<<4096, 128>>>();

    // u = LN(x) @ Wv + bv   (precomputed per token instead of per gathered neighbor)
    ln_k<<<2048, 256>>>(x, g1v, b1v, pln);
    gemm_k<false, 0><<<dim3(2, 128, 1), blk>>>(pln, Wv, bv, pu, 256, 256,
                                               nullptr, nullptr, 0, 0, 0, 0);
    // windowed attention combine -> o
    attn_k<<<512, 256>>>();

    // y1 = x + rw * (o @ Wo + bo)
    gemm_k<false, 3><<<dim3(2, 128, 1), blk>>>(po, Wo, bo, py1, 256, 256,
                                               x, rw, 0, 0, 0, 0);
    // FFN
    ln_k<<<2048, 256>>>(py1, gf, bf, pln);
    gemm_k<false, 2><<<dim3(8, 128, 1), blk>>>(pln, W1, b1f, ph, 256, 1024,
                                               nullptr, nullptr, 0, 0, 0, 0);
    gemm_k<false, 3><<<dim3(2, 128, 1), blk>>>(ph, W2, b2f, out, 1024, 256,
                                               py1, rw, 0, 0, 0, 0);
}

// round 3
// speedup vs baseline: 1.5050x; 1.5050x over previous
#include <cuda_runtime.h>
#include <cuda_bf16.h>
#include <math.h>
#include <float.h>
#include <stdint.h>

#define BTOT 8
#define SEQ  2048
#define MTOK (BTOT*SEQ)   /* 16384 */
#define DM   256
#define DQK  128
#define NH   8
#define DH   16
#define DV   32
#define NKNN 16
#define DFF  1024

// ---------------- scratch (static device globals; no allocations) ----------------
__device__ float g_q  [MTOK*DQK];
__device__ float g_k  [MTOK*DQK];
__device__ float g_kk [MTOK];
__device__ float g_S  [33554432];      // 8 * 2048 * 2048
__device__ int   g_idx[MTOK*NKNN];
__device__ float g_u  [MTOK*DM];
__device__ float g_y1 [MTOK*DM];

// bf16 hi/lo pair buffers
__device__ __nv_bfloat16 g_xh [MTOK*DM],  g_xl [MTOK*DM];
__device__ __nv_bfloat16 g_lnh[MTOK*DM],  g_lnl[MTOK*DM];
__device__ __nv_bfloat16 g_qph[MTOK*DQK], g_qpl[MTOK*DQK];
__device__ __nv_bfloat16 g_kph[MTOK*DQK], g_kpl[MTOK*DQK];
__device__ __nv_bfloat16 g_oh [MTOK*DM],  g_ol [MTOK*DM];
__device__ __nv_bfloat16 g_hh [MTOK*DFF], g_hl [MTOK*DFF];
// transposed weights [N,K] as bf16 pairs
__device__ __nv_bfloat16 g_wqh[DQK*DM],  g_wql[DQK*DM];
__device__ __nv_bfloat16 g_wkh[DQK*DM],  g_wkl[DQK*DM];
__device__ __nv_bfloat16 g_wvh[DM*DM],   g_wvl[DM*DM];
__device__ __nv_bfloat16 g_woh[DM*DM],   g_wol[DM*DM];
__device__ __nv_bfloat16 g_w1h[DFF*DM],  g_w1l[DFF*DM];
__device__ __nv_bfloat16 g_w2h[DM*DFF],  g_w2l[DM*DFF];

// ---------------- PTX helpers -------------------------------------------------------
__device__ __forceinline__ uint32_t smem_u32(const void* p) {
    uint32_t a;
    asm("{ .reg .u64 t; cvta.to.shared.u64 t, %1; cvt.u32.u64 %0, t; }" : "=r"(a) : "l"(p));
    return a;
}
#define LDSM4(r0, r1, r2, r3, a) \
    asm volatile("ldmatrix.sync.aligned.m8n8.x4.shared.b16 {%0,%1,%2,%3}, [%4];" \
                 : "=r"(r0), "=r"(r1), "=r"(r2), "=r"(r3) : "r"(a))
#define MMA16816(c, a, b) \
    asm volatile("mma.sync.aligned.m16n8k16.row.col.f32.bf16.bf16.f32 " \
                 "{%0,%1,%2,%3}, {%4,%5,%6,%7}, {%8,%9}, {%0,%1,%2,%3};" \
                 : "+f"((c)[0]), "+f"((c)[1]), "+f"((c)[2]), "+f"((c)[3]) \
                 : "r"((a)[0]), "r"((a)[1]), "r"((a)[2]), "r"((a)[3]), \
                   "r"((b)[0]), "r"((b)[1]))
#define CP_COMMIT() asm volatile("cp.async.commit_group;" ::: "memory")
#define CP_WAIT1()  asm volatile("cp.async.wait_group 1;" ::: "memory")
#define CP_WAIT0()  asm volatile("cp.async.wait_group 0;" ::: "memory")

// stage one 128x64-bf16 tile (128B rows, SW128 swizzle) via cp.async, 256 threads
__device__ __forceinline__ void stage_tile(uint32_t dst, const __nv_bfloat16* src,
                                           int ldK, int tid) {
#pragma unroll
    for (int j = 0; j < 4; j++) {
        int u = tid + j * 256;
        int row = u >> 3, seg = u & 7;
        uint32_t off = (uint32_t)(row * 128 + seg * 16);
        off ^= ((off >> 3) & 0x70);
        const void* gp = (const void*)(src + (long long)row * ldK + seg * 8);
        asm volatile("cp.async.cg.shared.global [%0], [%1], 16;"
                     :: "r"(dst + off), "l"(gp) : "memory");
    }
}

// ---------------- bf16x3 mma.sync GEMM: C(128x128/blk) = A·Bᵀ, fp32 acc -----------
// A: [M,K] K-major bf16 pairs. B: [N,K] K-major bf16 pairs. K multiple of 64.
// EPI: 0 = acc+bias -> f32 ; 1 = extra[col]-2*acc -> f32 ;
//      2 = gelu(acc+bias) -> bf16 pair ; 3 = extra[row,col]+rw*(acc+bias) -> f32
#define STAGE_BYTES 65536
#define SMEM_BYTES  (2 * STAGE_BYTES)

template<int EPI>
__global__ void __launch_bounds__(256)
mma_gemm(const __nv_bfloat16* __restrict__ Ah, const __nv_bfloat16* __restrict__ Al,
         const __nv_bfloat16* __restrict__ Bh, const __nv_bfloat16* __restrict__ Bl,
         const float* __restrict__ bias, float* __restrict__ C,
         __nv_bfloat16* __restrict__ Ch, __nv_bfloat16* __restrict__ Cl,
         int Kdim, int Ndim,
         const float* __restrict__ extra, const float* __restrict__ rwp,
         long long sAz, long long sBz, long long sCz, long long sEz)
{
    extern __shared__ __align__(128) char smem[];
    const uint32_t sb = smem_u32(smem);
    const int tid = threadIdx.x, lane = tid & 31, wid = tid >> 5;
    const int wm = wid & 1, wn = wid >> 1;
    const int bz = blockIdx.z;
    Ah += bz * sAz; Al += bz * sAz;
    Bh += bz * sBz; Bl += bz * sBz;
    if (EPI != 2) C += bz * sCz;
    if (EPI == 1) extra += bz * sEz;
    const int m0 = blockIdx.y * 128, n0 = blockIdx.x * 128;

    const __nv_bfloat16* A0h = Ah + (long long)m0 * Kdim;
    const __nv_bfloat16* A0l = Al + (long long)m0 * Kdim;
    const __nv_bfloat16* B0h = Bh + (long long)n0 * Kdim;
    const __nv_bfloat16* B0l = Bl + (long long)n0 * Kdim;

    float acc[4][4][4];
#pragma unroll
    for (int f = 0; f < 4; f++)
#pragma unroll
        for (int j = 0; j < 4; j++)
#pragma unroll
            for (int e = 0; e < 4; e++) acc[f][j][e] = 0.0f;

    const int nch = Kdim >> 6;

    // prefetch chunk 0 into stage 0
    {
        uint32_t s = sb;
        stage_tile(s,         A0h, Kdim, tid);
        stage_tile(s + 16384, A0l, Kdim, tid);
        stage_tile(s + 32768, B0h, Kdim, tid);
        stage_tile(s + 49152, B0l, Kdim, tid);
        CP_COMMIT();
    }

    const int lr = lane & 15;        // ldmatrix row within 16
    const int lcb = (lane >> 4) * 16; // byte offset selecting k0-7 vs k8-15 unit

    for (int c = 0; c < nch; c++) {
        if (c + 1 < nch) {
            uint32_t s = sb + ((c + 1) & 1) * STAGE_BYTES;
            int k0 = (c + 1) << 6;
            stage_tile(s,         A0h + k0, Kdim, tid);
            stage_tile(s + 16384, A0l + k0, Kdim, tid);
            stage_tile(s + 32768, B0h + k0, Kdim, tid);
            stage_tile(s + 49152, B0l + k0, Kdim, tid);
            CP_COMMIT();
            CP_WAIT1();
        } else {
            CP_WAIT0();
        }
        __syncthreads();

        const uint32_t base = sb + (c & 1) * STAGE_BYTES;
#pragma unroll
        for (int s = 0; s < 4; s++) {       // four k16 steps within the 64-k chunk
            const int kb = s * 32 + lcb;
            uint32_t ah[4][4], al_[4][4];
#pragma unroll
            for (int f = 0; f < 4; f++) {
                uint32_t off = (uint32_t)((wm * 64 + f * 16 + lr) * 128 + kb);
                off ^= ((off >> 3) & 0x70);
                LDSM4(ah[f][0], ah[f][1], ah[f][2], ah[f][3], base + off);
                LDSM4(al_[f][0], al_[f][1], al_[f][2], al_[f][3], base + 16384 + off);
            }
            uint32_t bh[4][2], bl_[4][2];
#pragma unroll
            for (int p = 0; p < 2; p++) {
                uint32_t off = (uint32_t)((wn * 32 + p * 16 + lr) * 128 + kb);
                off ^= ((off >> 3) & 0x70);
                uint32_t r0, r1, r2, r3;
                LDSM4(r0, r1, r2, r3, base + 32768 + off);
                bh[p * 2][0] = r0; bh[p * 2][1] = r2;
                bh[p * 2 + 1][0] = r1; bh[p * 2 + 1][1] = r3;
                LDSM4(r0, r1, r2, r3, base + 49152 + off);
                bl_[p * 2][0] = r0; bl_[p * 2][1] = r2;
                bl_[p * 2 + 1][0] = r1; bl_[p * 2 + 1][1] = r3;
            }
#pragma unroll
            for (int f = 0; f < 4; f++)
#pragma unroll
                for (int j = 0; j < 4; j++) {
                    MMA16816(acc[f][j], ah[f], bh[j]);
                    MMA16816(acc[f][j], ah[f], bl_[j]);
                    MMA16816(acc[f][j], al_[f], bh[j]);
                }
        }
        __syncthreads();
    }

    // ---------------- epilogue ----------------
    const int g = lane >> 2, t = lane & 3;
    const float rw = (EPI == 3) ? rwp[0] : 0.0f;
#pragma unroll
    for (int f = 0; f < 4; f++) {
        const int row0 = m0 + wm * 64 + f * 16 + g;
#pragma unroll
        for (int j = 0; j < 4; j++) {
            const int col = n0 + wn * 32 + j * 8 + t * 2;
#pragma unroll
            for (int h2 = 0; h2 < 2; h2++) {
                const int row = row0 + h2 * 8;
                float v0 = acc[f][j][h2 * 2 + 0];
                float v1 = acc[f][j][h2 * 2 + 1];
                if (EPI == 2) {
                    v0 += bias[col]; v1 += bias[col + 1];
                    v0 = 0.5f * v0 * (1.0f + erff(v0 * 0.7071067811865476f));
                    v1 = 0.5f * v1 * (1.0f + erff(v1 * 0.7071067811865476f));
                    long long bidx = (long long)row * Ndim + col;
                    __nv_bfloat16 h0 = __float2bfloat16(v0);
                    __nv_bfloat16 h1 = __float2bfloat16(v1);
                    Ch[bidx] = h0; Ch[bidx + 1] = h1;
                    Cl[bidx]     = __float2bfloat16(v0 - __bfloat162float(h0));
                    Cl[bidx + 1] = __float2bfloat16(v1 - __bfloat162float(h1));
                } else {
                    if (EPI == 0) { v0 += bias[col]; v1 += bias[col + 1]; }
                    else if (EPI == 1) {
                        v0 = extra[col] - 2.0f * v0;
                        v1 = extra[col + 1] - 2.0f * v1;
                    } else {
                        long long eidx = (long long)row * Ndim + col;
                        v0 = extra[eidx] + rw * (v0 + bias[col]);
                        v1 = extra[eidx + 1] + rw * (v1 + bias[col + 1]);
                    }
                    float2 vv = make_float2(v0, v1);
                    *(float2*)(C + (long long)row * Ndim + col) = vv;
                }
            }
        }
    }
}

// ---------------- f32 -> bf16 hi/lo pair conversion --------------------------------
__global__ void __launch_bounds__(256)
cvt_pair(const float* __restrict__ in, __nv_bfloat16* __restrict__ h,
         __nv_bfloat16* __restrict__ l, int n)
{
    int i = blockIdx.x * 256 + threadIdx.x;
    if (i >= n) return;
    float v = in[i];
    __nv_bfloat16 hh = __float2bfloat16(v);
    h[i] = hh;
    l[i] = __float2bfloat16(v - __bfloat162float(hh));
}

// ---------------- weight transpose+split: W[K,N] -> Wt[N,K] bf16 pairs -------------
__global__ void __launch_bounds__(256)
wconv(const float* __restrict__ W, __nv_bfloat16* __restrict__ Th,
      __nv_bfloat16* __restrict__ Tl, int K, int N)
{
    int i = blockIdx.x * 256 + threadIdx.x;
    if (i >= K * N) return;
    int k = i / N, n = i % N;
    float v = W[i];
    __nv_bfloat16 h = __float2bfloat16(v);
    Th[(long long)n * K + k] = h;
    Tl[(long long)n * K + k] = __float2bfloat16(v - __bfloat162float(h));
}

// ---------------- l2 normalize q & k rows (in place) + pairs, kk = ||kn||^2 --------
__global__ void __launch_bounds__(256) l2norm_k()
{
    int gw = (blockIdx.x * blockDim.x + threadIdx.x) >> 5;
    int lane = threadIdx.x & 31;
    if (gw >= 2 * MTOK) return;
    bool isq = (gw < MTOK);
    long long rowi = isq ? gw : (gw - MTOK);
    float* base = (isq ? g_q : g_k) + rowi * DQK;
    float4 v = *(float4*)(base + lane * 4);
    float ss = v.x * v.x + v.y * v.y + v.z * v.z + v.w * v.w;
#pragma unroll
    for (int o = 16; o; o >>= 1) ss += __shfl_xor_sync(0xffffffffu, ss, o);
    float inv = 1.0f / fmaxf(sqrtf(ss), 1e-12f);
    v.x *= inv; v.y *= inv; v.z *= inv; v.w *= inv;
    *(float4*)(base + lane * 4) = v;
    __nv_bfloat16* ph = (isq ? g_qph : g_kph) + rowi * DQK + lane * 4;
    __nv_bfloat16* pl = (isq ? g_qpl : g_kpl) + rowi * DQK + lane * 4;
    float e[4] = {v.x, v.y, v.z, v.w};
#pragma unroll
    for (int j = 0; j < 4; j++) {
        __nv_bfloat16 h = __float2bfloat16(e[j]);
        ph[j] = h;
        pl[j] = __float2bfloat16(e[j] - __bfloat162float(h));
    }
    if (!isq) {
        float s2 = v.x * v.x + v.y * v.y + v.z * v.z + v.w * v.w;
#pragma unroll
        for (int o = 16; o; o >>= 1) s2 += __shfl_xor_sync(0xffffffffu, s2, o);
        if (lane == 0) g_kk[rowi] = s2;
    }
}

// ---------------- LayerNorm over D=256 (warp per row) -> bf16 pairs ----------------
__global__ void __launch_bounds__(256)
ln_k(const float* __restrict__ in, const float* __restrict__ g,
     const float* __restrict__ b, __nv_bfloat16* __restrict__ oh,
     __nv_bfloat16* __restrict__ ol)
{
    int gw = (blockIdx.x * blockDim.x + threadIdx.x) >> 5;
    int lane = threadIdx.x & 31;
    if (gw >= MTOK) return;
    const float* r = in + (long long)gw * DM;
    float4 a0 = *(const float4*)(r + lane * 8);
    float4 a1 = *(const float4*)(r + lane * 8 + 4);
    float s = a0.x + a0.y + a0.z + a0.w + a1.x + a1.y + a1.z + a1.w;
#pragma unroll
    for (int o = 16; o; o >>= 1) s += __shfl_xor_sync(0xffffffffu, s, o);
    float mean = s * (1.0f / 256.0f);
    float d[8] = {a0.x - mean, a0.y - mean, a0.z - mean, a0.w - mean,
                  a1.x - mean, a1.y - mean, a1.z - mean, a1.w - mean};
    float vs = 0.0f;
#pragma unroll
    for (int j = 0; j < 8; j++) vs += d[j] * d[j];
#pragma unroll
    for (int o = 16; o; o >>= 1) vs += __shfl_xor_sync(0xffffffffu, vs, o);
    float is = rsqrtf(vs * (1.0f / 256.0f) + 1e-5f);
    int c = lane * 8;
    long long base = (long long)gw * DM + c;
#pragma unroll
    for (int j = 0; j < 8; j++) {
        float v = d[j] * is * g[c + j] + b[c + j];
        __nv_bfloat16 h = __float2bfloat16(v);
        oh[base + j] = h;
        ol[base + j] = __float2bfloat16(v - __bfloat162float(h));
    }
}

// ---------------- top-16 smallest per score row (warp per row, smem staged) --------
__global__ void __launch_bounds__(128) topk_k()
{
    __shared__ float srow[4][SEQ];
    int wid = threadIdx.x >> 5, lane = threadIdx.x & 31;
    long long row = (long long)blockIdx.x * 4 + wid;
    const float* Sr = g_S + row * SEQ;
    float* sm = srow[wid];
    for (int c = lane; c < SEQ / 4; c += 32)
        *(float4*)(sm + c * 4) = *(const float4*)(Sr + c * 4);
    __syncwarp();
    int* orow = g_idx + row * NKNN;
    for (int r = 0; r < NKNN; r++) {
        float best = FLT_MAX; int bi = 0x7fffffff;
        for (int c = lane; c < SEQ; c += 32) {
            float s = sm[c];
            if (s < best || (s == best && c < bi)) { best = s; bi = c; }
        }
#pragma unroll
        for (int o = 16; o; o >>= 1) {
            float s2 = __shfl_xor_sync(0xffffffffu, best, o);
            int   i2 = __shfl_xor_sync(0xffffffffu, bi, o);
            if (s2 < best || (s2 == best && i2 < bi)) { best = s2; bi = i2; }
        }
        if (lane == 0) { orow[r] = bi; sm[bi] = FLT_MAX; }
        __syncwarp();
    }
}

// ---------------- attention combine -> o as bf16 pairs -----------------------------
__global__ void __launch_bounds__(256) attn_k()
{
    int t = blockIdx.x * 256 + threadIdx.x;
    int token = t >> 3, h = t & 7;
    if (token >= MTOK) return;
    long long kbase = (long long)(token >> 11) * SEQ;

    const float* qp = g_q + (long long)token * DQK + h * DH;
    float q[16];
#pragma unroll
    for (int i = 0; i < 4; i++)
        *(float4*)&q[i * 4] = *(const float4*)(qp + i * 4);

    const int* ir = g_idx + (long long)token * NKNN;
    int nb[NKNN];
#pragma unroll
    for (int j = 0; j < NKNN; j++) nb[j] = ir[j];

    float lg[NKNN];
#pragma unroll
    for (int j = 0; j < NKNN; j++) {
        const float* kr = g_k + (kbase + nb[j]) * DQK + h * DH;
        float d = 0.0f;
#pragma unroll
        for (int i = 0; i < 4; i++) {
            float4 kv = *(const float4*)(kr + i * 4);
            d += q[i*4+0]*kv.x + q[i*4+1]*kv.y + q[i*4+2]*kv.z + q[i*4+3]*kv.w;
        }
        lg[j] = d * 0.25f;   // 1/sqrt(16)
    }
    float mx = lg[0];
#pragma unroll
    for (int j = 1; j < NKNN; j++) mx = fmaxf(mx, lg[j]);
    float se = 0.0f;
#pragma unroll
    for (int j = 0; j < NKNN; j++) { lg[j] = expf(lg[j] - mx); se += lg[j]; }
    float inv = 1.0f / se;

    float acc[32];
#pragma unroll
    for (int e = 0; e < 32; e++) acc[e] = 0.0f;
#pragma unroll
    for (int j = 0; j < NKNN; j++) {
        float w = lg[j] * inv;
        const float* ur = g_u + (kbase + nb[j]) * DM + h * DV;
#pragma unroll
        for (int i = 0; i < 8; i++) {
            float4 uv = *(const float4*)(ur + i * 4);
            acc[i*4+0] += w * uv.x; acc[i*4+1] += w * uv.y;
            acc[i*4+2] += w * uv.z; acc[i*4+3] += w * uv.w;
        }
    }
    long long obase = (long long)token * DM + h * DV;
#pragma unroll
    for (int e = 0; e < 32; e++) {
        __nv_bfloat16 hh = __float2bfloat16(acc[e]);
        g_oh[obase + e] = hh;
        g_ol[obase + e] = __float2bfloat16(acc[e] - __bfloat162float(hh));
    }
}

// ---------------- launch sequence ---------------------------------------------------
extern "C" void kernel_launch(void* const* d_in, const int* in_sizes, int n_in,
                              void* d_out, int out_size)
{
    const float* x   = (const float*)d_in[0];
    const float* Wq  = (const float*)d_in[1];
    const float* bq  = (const float*)d_in[2];
    const float* Wk  = (const float*)d_in[3];
    const float* bk  = (const float*)d_in[4];
    const float* Wv  = (const float*)d_in[5];
    const float* bv  = (const float*)d_in[6];
    const float* Wo  = (const float*)d_in[7];
    const float* bo  = (const float*)d_in[8];
    const float* g1v = (const float*)d_in[9];
    const float* b1v = (const float*)d_in[10];
    const float* gf  = (const float*)d_in[11];
    const float* bf  = (const float*)d_in[12];
    const float* W1  = (const float*)d_in[13];
    const float* b1f = (const float*)d_in[14];
    const float* W2  = (const float*)d_in[15];
    const float* b2f = (const float*)d_in[16];
    const float* rw  = (const float*)d_in[17];
    float* out = (float*)d_out;

    cudaFuncSetAttribute(mma_gemm<0>, cudaFuncAttributeMaxDynamicSharedMemorySize, SMEM_BYTES);
    cudaFuncSetAttribute(mma_gemm<1>, cudaFuncAttributeMaxDynamicSharedMemorySize, SMEM_BYTES);
    cudaFuncSetAttribute(mma_gemm<2>, cudaFuncAttributeMaxDynamicSharedMemorySize, SMEM_BYTES);
    cudaFuncSetAttribute(mma_gemm<3>, cudaFuncAttributeMaxDynamicSharedMemorySize, SMEM_BYTES);

    float *pq, *pk, *pkk, *pS, *pu, *py1;
    cudaGetSymbolAddress((void**)&pq,  g_q);
    cudaGetSymbolAddress((void**)&pk,  g_k);
    cudaGetSymbolAddress((void**)&pkk, g_kk);
    cudaGetSymbolAddress((void**)&pS,  g_S);
    cudaGetSymbolAddress((void**)&pu,  g_u);
    cudaGetSymbolAddress((void**)&py1, g_y1);

    __nv_bfloat16 *xh, *xl, *lnh, *lnl, *qph, *qpl, *kph, *kpl, *oh, *ol, *hh, *hl;
    __nv_bfloat16 *wqh, *wql, *wkh, *wkl, *wvh, *wvl, *woh, *wol, *w1h, *w1l, *w2h, *w2l;
    cudaGetSymbolAddress((void**)&xh,  g_xh);  cudaGetSymbolAddress((void**)&xl,  g_xl);
    cudaGetSymbolAddress((void**)&lnh, g_lnh); cudaGetSymbolAddress((void**)&lnl, g_lnl);
    cudaGetSymbolAddress((void**)&qph, g_qph); cudaGetSymbolAddress((void**)&qpl, g_qpl);
    cudaGetSymbolAddress((void**)&kph, g_kph); cudaGetSymbolAddress((void**)&kpl, g_kpl);
    cudaGetSymbolAddress((void**)&oh,  g_oh);  cudaGetSymbolAddress((void**)&ol,  g_ol);
    cudaGetSymbolAddress((void**)&hh,  g_hh);  cudaGetSymbolAddress((void**)&hl,  g_hl);
    cudaGetSymbolAddress((void**)&wqh, g_wqh); cudaGetSymbolAddress((void**)&wql, g_wql);
    cudaGetSymbolAddress((void**)&wkh, g_wkh); cudaGetSymbolAddress((void**)&wkl, g_wkl);
    cudaGetSymbolAddress((void**)&wvh, g_wvh); cudaGetSymbolAddress((void**)&wvl, g_wvl);
    cudaGetSymbolAddress((void**)&woh, g_woh); cudaGetSymbolAddress((void**)&wol, g_wol);
    cudaGetSymbolAddress((void**)&w1h, g_w1h); cudaGetSymbolAddress((void**)&w1l, g_w1l);
    cudaGetSymbolAddress((void**)&w2h, g_w2h); cudaGetSymbolAddress((void**)&w2l, g_w2l);

    // weight transpose + split, x split
    wconv<<<(DM*DQK + 255) / 256, 256>>>(Wq, wqh, wql, DM, DQK);
    wconv<<<(DM*DQK + 255) / 256, 256>>>(Wk, wkh, wkl, DM, DQK);
    wconv<<<(DM*DM  + 255) / 256, 256>>>(Wv, wvh, wvl, DM, DM);
    wconv<<<(DM*DM  + 255) / 256, 256>>>(Wo, woh, wol, DM, DM);
    wconv<<<(DM*DFF + 255) / 256, 256>>>(W1, w1h, w1l, DM, DFF);
    wconv<<<(DFF*DM + 255) / 256, 256>>>(W2, w2h, w2l, DFF, DM);
    cvt_pair<<<(MTOK*DM) / 256, 256>>>(x, xh, xl, MTOK * DM);

    // q / k projections: [16384,256] @ Wq/Wk -> f32
    mma_gemm<0><<<dim3(1, 128, 1), 256, SMEM_BYTES>>>(xh, xl, wqh, wql, bq, pq,
        nullptr, nullptr, DM, DQK, nullptr, nullptr, 0, 0, 0, 0);
    mma_gemm<0><<<dim3(1, 128, 1), 256, SMEM_BYTES>>>(xh, xl, wkh, wkl, bk, pk,
        nullptr, nullptr, DM, DQK, nullptr, nullptr, 0, 0, 0, 0);
    // l2 normalize (in-place f32 + bf16 pairs + kk)
    l2norm_k<<<4096, 256>>>();

    // scores: per batch S = kk[col] - 2 * qn @ kn^T
    mma_gemm<1><<<dim3(16, 16, 8), 256, SMEM_BYTES>>>(qph, qpl, kph, kpl, nullptr, pS,
        nullptr, nullptr, DQK, SEQ, pkk, nullptr,
        (long long)SEQ * DQK, (long long)SEQ * DQK,
        (long long)SEQ * SEQ, (long long)SEQ);
    topk_k<<<4096, 128>>>();

    // u = LN(x) @ Wv + bv
    ln_k<<<2048, 256>>>(x, g1v, b1v, lnh, lnl);
    mma_gemm<0><<<dim3(2, 128, 1), 256, SMEM_BYTES>>>(lnh, lnl, wvh, wvl, bv, pu,
        nullptr, nullptr, DM, DM, nullptr, nullptr, 0, 0, 0, 0);
    attn_k<<<512, 256>>>();

    // y1 = x + rw * (o @ Wo + bo)
    mma_gemm<3><<<dim3(2, 128, 1), 256, SMEM_BYTES>>>(oh, ol, woh, wol, bo, py1,
        nullptr, nullptr, DM, DM, x, rw, 0, 0, 0, 0);
    // FFN
    ln_k<<<2048, 256>>>(py1, gf, bf, lnh, lnl);
    mma_gemm<2><<<dim3(8, 128, 1), 256, SMEM_BYTES>>>(lnh, lnl, w1h, w1l, b1f, nullptr,
        hh, hl, DM, DFF, nullptr, nullptr, 0, 0, 0, 0);
    mma_gemm<3><<<dim3(2, 128, 1), 256, SMEM_BYTES>>>(hh, hl, w2h, w2l, b2f, out,
        nullptr, nullptr, DFF, DM, py1, rw, 0, 0, 0, 0);
}